// round 1
// baseline (speedup 1.0000x reference)
#include <cuda_runtime.h>

// Problem constants
#define NIMG   64
#define IMGS   224
#define GDIM   14
#define PSZ    16
#define DDIM   768      // output dim
#define KCLS   768      // per-class K = 16*16*3
#define ROWEL  (IMGS*3) // 672 floats per image row

// 9 precomputed class-effective weight matrices: 9 * 768 * 768 * 4B = 21.2 MB scratch
__device__ float g_Wc[9][KCLS * DDIM];

// ---------------------------------------------------------------------------
// Kernel 1: build per-class effective weights.
// class = 3*clsH + clsW,  clsH: 0 -> gh==0, 1 -> gh in [1,12], 2 -> gh==13
// For patch-pixel (ph,pw) inside a patch of that class, the global pixel falls
// in row-region th (0=TOP h<8, 1=MID, 2=BOT h>=216) and col-region tw.
// Group activity (group g row index in W = pp*15 + 3g + cin):
//   g0 (raw image)      : always
//   g1 (oh=0, ow=0)     : inactive iff th==BOT || tw==BOT
//   g2 (oh=8, ow=0)     : inactive iff th==TOP || tw==BOT
//   g3 (oh=0, ow=8)     : inactive iff th==BOT || tw==TOP
//   g4 (oh=8, ow=8)     : inactive iff th==TOP || tw==TOP
// ---------------------------------------------------------------------------
__global__ void build_wc_kernel(const float* __restrict__ W) {
    int blk  = blockIdx.x;            // 0 .. 9*768-1
    int cls  = blk / KCLS;
    int k    = blk % KCLS;            // (ph,pw,cin), cin fastest
    int clsH = cls / 3, clsW = cls % 3;
    int pp   = k / 3,  cin = k % 3;
    int ph   = pp / PSZ, pw = pp % PSZ;

    int th = (clsH == 0 && ph < 8) ? 0 : (clsH == 2 && ph >= 8) ? 2 : 1;
    int tw = (clsW == 0 && pw < 8) ? 0 : (clsW == 2 && pw >= 8) ? 2 : 1;

    bool inc[5];
    inc[0] = true;
    inc[1] = !(th == 2 || tw == 2);
    inc[2] = !(th == 0 || tw == 2);
    inc[3] = !(th == 2 || tw == 0);
    inc[4] = !(th == 0 || tw == 0);

    const float* wbase = W + (size_t)(pp * 15 + cin) * DDIM;
    float* dst = g_Wc[cls] + (size_t)k * DDIM;

    for (int n = threadIdx.x; n < DDIM; n += blockDim.x) {
        float s = 0.f;
        #pragma unroll
        for (int g = 0; g < 5; g++)
            if (inc[g]) s += wbase[(size_t)(3 * g) * DDIM + n];
        dst[n] = s;
    }
}

// ---------------------------------------------------------------------------
// Kernel 2: class-partitioned SGEMM.
//   out[m, n] = A[m, :] @ g_Wc[class(m)] + bias[n]
// A (generated on the fly): A[(b,gh,gw), (ph,pw,cin)] = img[b, 16gh+ph, 16gw+pw, cin]
// Tile: 128x128, BK=8, 256 threads, 8x8 micro-tile per thread.
// Grid.x enumerates M-tiles across all 9 classes (100 total), grid.y = N tiles (6).
// ---------------------------------------------------------------------------
#define BM 128
#define BN 128
#define BK 8
#define TM 8
#define TN 8

__global__ __launch_bounds__(256, 2)
void class_gemm_kernel(const float* __restrict__ img,
                       const float* __restrict__ bias,
                       float* __restrict__ out) {
    // per-class geometry (compile-time-ish tables)
    const int nhv[3]  = {1, 12, 1};
    const int ghbv[3] = {0, 1, 13};

    // map blockIdx.x -> (class, local m-tile)
    int mtl = blockIdx.x;
    int cls = 8;
    #pragma unroll
    for (int c = 0; c < 9; c++) {
        int tiles = (NIMG * nhv[c / 3] * nhv[c % 3] + BM - 1) / BM;
        if (mtl < tiles) { cls = c; break; }
        mtl -= tiles;
    }
    int clsH = cls / 3, clsW = cls % 3;
    int nh  = nhv[clsH], nw = nhv[clsW];
    int ghb = ghbv[clsH], gwb = ghbv[clsW];
    int rpi = nh * nw;             // patches per image in this class
    int Mc  = NIMG * rpi;          // rows in this class
    int m0  = mtl * BM;
    int n0  = blockIdx.y * BN;

    __shared__ __align__(16) float As[BK][BM];
    __shared__ __align__(16) float Bs[BK][BN];

    int t = threadIdx.x;

    // A-load mapping: thread -> (row, 4-wide k chunk)
    int arow = t >> 1;
    int asub = (t & 1) * 4;
    int am = m0 + arow;
    bool avalid = am < Mc;
    int rowbase = 0;
    {
        int mm = avalid ? am : 0;
        int bimg = mm / rpi;
        int r    = mm % rpi;
        int gh   = ghb + r / nw;
        int gw   = gwb + r % nw;
        rowbase = (bimg * IMGS + gh * PSZ) * ROWEL + gw * (PSZ * 3);
    }

    // B-load mapping
    int brow = t >> 5;        // 0..7
    int bcol = (t & 31) * 4;  // 0..124
    const float* Wc = g_Wc[cls];

    float acc[TM][TN];
    #pragma unroll
    for (int i = 0; i < TM; i++)
        #pragma unroll
        for (int j = 0; j < TN; j++) acc[i][j] = 0.f;

    int tx = t & 15;   // 16 threads over N
    int ty = t >> 4;   // 16 threads over M

    for (int kt = 0; kt < KCLS; kt += BK) {
        // --- load A tile (rows of patches; 4 consecutive k are contiguous in
        //     HWC memory since cin is fastest and 48 | boundaries) ---
        int k   = kt + asub;
        int ph  = k / 48;
        int rem = k - ph * 48;    // pw*3 + cin
        float4 av = make_float4(0.f, 0.f, 0.f, 0.f);
        if (avalid)
            av = *reinterpret_cast<const float4*>(img + rowbase + ph * ROWEL + rem);
        As[asub + 0][arow] = av.x;
        As[asub + 1][arow] = av.y;
        As[asub + 2][arow] = av.z;
        As[asub + 3][arow] = av.w;

        // --- load B tile ---
        float4 bv = *reinterpret_cast<const float4*>(
            Wc + (size_t)(kt + brow) * DDIM + n0 + bcol);
        *reinterpret_cast<float4*>(&Bs[brow][bcol]) = bv;

        __syncthreads();

        #pragma unroll
        for (int kk = 0; kk < BK; kk++) {
            float4 a0 = *reinterpret_cast<const float4*>(&As[kk][ty * TM]);
            float4 a1 = *reinterpret_cast<const float4*>(&As[kk][ty * TM + 4]);
            float4 b0 = *reinterpret_cast<const float4*>(&Bs[kk][tx * TN]);
            float4 b1 = *reinterpret_cast<const float4*>(&Bs[kk][tx * TN + 4]);
            float af[TM] = {a0.x, a0.y, a0.z, a0.w, a1.x, a1.y, a1.z, a1.w};
            float bf[TN] = {b0.x, b0.y, b0.z, b0.w, b1.x, b1.y, b1.z, b1.w};
            #pragma unroll
            for (int i = 0; i < TM; i++)
                #pragma unroll
                for (int j = 0; j < TN; j++)
                    acc[i][j] += af[i] * bf[j];
        }
        __syncthreads();
    }

    // --- epilogue: bias + scatter rows back to (b, patch) ordering ---
    float bvv[TN];
    #pragma unroll
    for (int j = 0; j < TN; j++) bvv[j] = bias[n0 + tx * TN + j];

    #pragma unroll
    for (int i = 0; i < TM; i++) {
        int m = m0 + ty * TM + i;
        if (m < Mc) {
            int bimg = m / rpi;
            int r    = m % rpi;
            int gh   = ghb + r / nw;
            int gw   = gwb + r % nw;
            size_t o = ((size_t)bimg * (GDIM * GDIM) + gh * GDIM + gw) * DDIM
                     + n0 + tx * TN;
            #pragma unroll
            for (int j = 0; j < TN; j++)
                out[o + j] = acc[i][j] + bvv[j];
        }
    }
}

// ---------------------------------------------------------------------------
extern "C" void kernel_launch(void* const* d_in, const int* in_sizes, int n_in,
                              void* d_out, int out_size) {
    const float* images = (const float*)d_in[0];
    const float* W      = (const float*)d_in[1];
    const float* bias   = (const float*)d_in[2];
    float* out          = (float*)d_out;

    // 1) build 9 class-effective weight matrices (tiny)
    build_wc_kernel<<<9 * KCLS, 256>>>(W);

    // 2) class-partitioned SGEMM. Total M-tiles:
    //    corners: 4*1, edges: 4*6, interior: 72  -> 100
    dim3 grid(100, DDIM / BN);
    class_gemm_kernel<<<grid, 256>>>(images, bias, out);
}

// round 3
// speedup vs baseline: 1.3877x; 1.3877x over previous
#include <cuda_runtime.h>
#include <cuda_bf16.h>
#include <cstdint>

// ---------------------------------------------------------------------------
// Problem constants
// ---------------------------------------------------------------------------
#define NIMG   64
#define IMGS   224
#define GDIM   14
#define PSZ    16
#define DDIM   768
#define KCLS   768            // per-class K = 16*16*3
#define ROWEL  (IMGS*3)       // 672 floats per image row

// GEMM tiling
#define BM      128
#define BN      128
#define BK      32
#define NCHUNKS (KCLS / BK)   // 24

// Per-class effective weights, bf16 2-way split, layout [cls][k][n] (n contig)
// 2 * 9 * 768 * 768 * 2B = 21.2 MB scratch
__device__ __align__(16) __nv_bfloat16 g_Bhi[9u * KCLS * DDIM];
__device__ __align__(16) __nv_bfloat16 g_Blo[9u * KCLS * DDIM];

// ---------------------------------------------------------------------------
// helpers
// ---------------------------------------------------------------------------
__device__ __forceinline__ uint32_t smem_u32(const void* p) {
    uint32_t a;
    asm("{ .reg .u64 t; cvta.to.shared.u64 t, %1; cvt.u32.u64 %0, t; }"
        : "=r"(a) : "l"(p));
    return a;
}

__device__ __forceinline__ void mma_bf16(float* c, const uint32_t* a, const uint32_t* b) {
    asm volatile(
        "mma.sync.aligned.m16n8k16.row.col.f32.bf16.bf16.f32 "
        "{%0,%1,%2,%3}, {%4,%5,%6,%7}, {%8,%9}, {%0,%1,%2,%3};"
        : "+f"(c[0]), "+f"(c[1]), "+f"(c[2]), "+f"(c[3])
        : "r"(a[0]), "r"(a[1]), "r"(a[2]), "r"(a[3]), "r"(b[0]), "r"(b[1]));
}

__device__ __forceinline__ void ldsm_x4(uint32_t* r, uint32_t addr) {
    asm volatile("ldmatrix.sync.aligned.m8n8.x4.shared.b16 {%0,%1,%2,%3}, [%4];"
                 : "=r"(r[0]), "=r"(r[1]), "=r"(r[2]), "=r"(r[3]) : "r"(addr));
}

__device__ __forceinline__ void ldsm_x2t(uint32_t* r, uint32_t addr) {
    asm volatile("ldmatrix.sync.aligned.m8n8.x2.trans.shared.b16 {%0,%1}, [%2];"
                 : "=r"(r[0]), "=r"(r[1]) : "r"(addr));
}

#define CP_ASYNC16(dst, src) \
    asm volatile("cp.async.cg.shared.global [%0], [%1], 16;" :: "r"(dst), "l"(src))
#define CP_COMMIT() asm volatile("cp.async.commit_group;" ::: "memory")
#define CP_WAIT0()  asm volatile("cp.async.wait_group 0;" ::: "memory")

__device__ __forceinline__ void split_pack(float a, float b,
                                           uint32_t& hi, uint32_t& lo) {
    __nv_bfloat16 ha = __float2bfloat16_rn(a);
    __nv_bfloat16 hb = __float2bfloat16_rn(b);
    __nv_bfloat16 la = __float2bfloat16_rn(a - __bfloat162float(ha));
    __nv_bfloat16 lb = __float2bfloat16_rn(b - __bfloat162float(hb));
    hi = ((uint32_t)__bfloat16_as_ushort(hb) << 16) | __bfloat16_as_ushort(ha);
    lo = ((uint32_t)__bfloat16_as_ushort(lb) << 16) | __bfloat16_as_ushort(la);
}

// ---------------------------------------------------------------------------
// Kernel 1: per-class effective weights, bf16 hi/lo split, layout [cls][k][n].
// grid = 9*768 blocks (cls,k), block = 384 threads (2 n each)
// ---------------------------------------------------------------------------
__global__ void build_w_kernel(const float* __restrict__ W) {
    int blk  = blockIdx.x;
    int cls  = blk / KCLS;
    int k    = blk % KCLS;
    int clsH = cls / 3, clsW = cls % 3;
    int pp   = k / 3,  cin = k % 3;
    int ph   = pp >> 4, pw = pp & 15;

    int th = (clsH == 0 && ph < 8) ? 0 : (clsH == 2 && ph >= 8) ? 2 : 1;
    int tw = (clsW == 0 && pw < 8) ? 0 : (clsW == 2 && pw >= 8) ? 2 : 1;
    bool i1 = !(th == 2 || tw == 2);
    bool i2 = !(th == 0 || tw == 2);
    bool i3 = !(th == 2 || tw == 0);
    bool i4 = !(th == 0 || tw == 0);

    const float* wb = W + (size_t)(pp * 15 + cin) * DDIM;
    int n = threadIdx.x * 2;

    float s0 = wb[n],     s1 = wb[n + 1];
    if (i1) { s0 += wb[3 * DDIM + n]; s1 += wb[3 * DDIM + n + 1]; }
    if (i2) { s0 += wb[6 * DDIM + n]; s1 += wb[6 * DDIM + n + 1]; }
    if (i3) { s0 += wb[9 * DDIM + n]; s1 += wb[9 * DDIM + n + 1]; }
    if (i4) { s0 += wb[12 * DDIM + n]; s1 += wb[12 * DDIM + n + 1]; }

    uint32_t hi, lo;
    split_pack(s0, s1, hi, lo);
    size_t o = ((size_t)cls * KCLS + k) * DDIM + n;
    *reinterpret_cast<uint32_t*>(&g_Bhi[o]) = hi;
    *reinterpret_cast<uint32_t*>(&g_Blo[o]) = lo;
}

// ---------------------------------------------------------------------------
// Kernel 2: class-partitioned bf16-split HMMA GEMM.
// CTA tile 128(M) x 128(N) x 768(K); BK=32, double-buffered.
// 8 warps: 2(m) x 4(n); warp tile 64x32; m16n8k16 fragments.
// ---------------------------------------------------------------------------
// SMEM (bytes), per stage:
//   Ahi 128x40h = 10240 | Alo 10240 | Bhi 32x136h = 8704 | Blo 8704
#define A_STRIDE_B 80     // bytes per A row (40 halves)
#define B_STRIDE_B 272    // bytes per B row (136 halves)
#define SZ_A 10240
#define SZ_B 8704
#define OFF_AHI 0
#define OFF_ALO 10240
#define OFF_BHI 20480
#define OFF_BLO 29184
#define STG     37888
#define SMEM_TOTAL (2 * STG)   // 75776

__global__ __launch_bounds__(256)
void class_gemm_hmma(const float* __restrict__ img,
                     const float* __restrict__ bias,
                     float* __restrict__ out) {
    extern __shared__ __align__(16) char smem[];
    const uint32_t sb = smem_u32(smem);

    const int nhv[3]  = {1, 12, 1};
    const int ghbv[3] = {0, 1, 13};

    // map blockIdx.x -> (class, local m-tile)
    int mtl = blockIdx.x;
    int cls = 8;
    #pragma unroll
    for (int c = 0; c < 9; c++) {
        int tiles_c = (NIMG * nhv[c / 3] * nhv[c % 3] + BM - 1) / BM;
        if (mtl < tiles_c) { cls = c; break; }
        mtl -= tiles_c;
    }
    const int clsH = cls / 3, clsW = cls % 3;
    const int nh = nhv[clsH], nw = nhv[clsW];
    const int ghb = ghbv[clsH], gwb = ghbv[clsW];
    const int rpi = nh * nw;
    const int Mc  = NIMG * rpi;
    const int m0  = mtl * BM;
    const int n0  = blockIdx.y * BN;

    const int t    = threadIdx.x;
    const int wid  = t >> 5, lane = t & 31;
    const int wm   = wid >> 2;        // warp m index (0..1)
    const int wn   = wid & 3;         // warp n index (0..3)
    const int gi   = lane >> 2;       // 0..7
    const int li   = lane & 3;        // 0..3
    const int l16  = lane & 15;
    const int lhi  = (lane >> 4) & 1;

    // A-load mapping: thread -> row t>>1, k-half (t&1)*16
    const int arow   = t >> 1;
    const int khalf  = t & 1;
    const int am     = m0 + arow;
    const bool avalid = am < Mc;
    int rowbase = 0;
    {
        int mm = avalid ? am : 0;
        int bimg = mm / rpi;
        int r    = mm % rpi;
        int gh   = ghb + r / nw;
        int gw   = gwb + r % nw;
        rowbase = (bimg * IMGS + gh * PSZ) * ROWEL + gw * (PSZ * 3);
    }

    const __nv_bfloat16* gBhi = g_Bhi + ((size_t)cls * KCLS) * DDIM + n0;
    const __nv_bfloat16* gBlo = g_Blo + ((size_t)cls * KCLS) * DDIM + n0;

    // ldmatrix base offsets (per thread)
    const uint32_t a_ld = (uint32_t)((wm * 64 + l16) * A_STRIDE_B + lhi * 16);
    const uint32_t b_ld = (uint32_t)(l16 * B_STRIDE_B + wn * 64);

    float acc[4][4][4];
    #pragma unroll
    for (int i = 0; i < 4; i++)
        #pragma unroll
        for (int j = 0; j < 4; j++)
            #pragma unroll
            for (int q = 0; q < 4; q++) acc[i][j][q] = 0.f;

    float4 areg[4];

    // ------------------- A gmem load into regs -------------------
    auto load_a = [&](int kt) {
        #pragma unroll
        for (int j = 0; j < 4; j++) {
            int k = kt + khalf * 16 + j * 4;
            if (avalid) {
                int phh = k / 48;
                int rem = k - phh * 48;
                areg[j] = *reinterpret_cast<const float4*>(img + rowbase + phh * ROWEL + rem);
            } else {
                areg[j] = make_float4(0.f, 0.f, 0.f, 0.f);
            }
        }
    };
    // ------------------- A convert + store -----------------------
    auto sts_a = [&](int buf) {
        uint32_t base = sb + buf * STG + (uint32_t)(arow * A_STRIDE_B + khalf * 32);
        #pragma unroll
        for (int j = 0; j < 4; j++) {
            uint32_t h0, l0, h1, l1;
            split_pack(areg[j].x, areg[j].y, h0, l0);
            split_pack(areg[j].z, areg[j].w, h1, l1);
            uint32_t off = base + j * 8;
            asm volatile("st.shared.v2.b32 [%0], {%1,%2};"
                         :: "r"(off + OFF_AHI), "r"(h0), "r"(h1) : "memory");
            asm volatile("st.shared.v2.b32 [%0], {%1,%2};"
                         :: "r"(off + OFF_ALO), "r"(l0), "r"(l1) : "memory");
        }
    };
    // ------------------- B cp.async -------------------------------
    auto load_b = [&](int kt, int buf) {
        uint32_t dbase = sb + buf * STG;
        #pragma unroll
        for (int i = 0; i < 2; i++) {
            int idx = i * 256 + t;       // 0..511
            int row = idx >> 4;
            int seg = idx & 15;
            const __nv_bfloat16* sh = gBhi + (size_t)(kt + row) * DDIM + seg * 8;
            const __nv_bfloat16* sl = gBlo + (size_t)(kt + row) * DDIM + seg * 8;
            uint32_t doff = (uint32_t)(row * B_STRIDE_B + seg * 16);
            CP_ASYNC16(dbase + OFF_BHI + doff, sh);
            CP_ASYNC16(dbase + OFF_BLO + doff, sl);
        }
    };

    // ------------------- prologue ---------------------------------
    load_a(0);
    load_b(0, 0);
    CP_COMMIT();
    sts_a(0);

    // ------------------- main loop --------------------------------
    for (int c = 0; c < NCHUNKS; c++) {
        int buf = c & 1;
        CP_WAIT0();
        __syncthreads();

        if (c + 1 < NCHUNKS) {
            load_a((c + 1) * BK);
            load_b((c + 1) * BK, buf ^ 1);
            CP_COMMIT();
        }

        uint32_t stg = sb + buf * STG;
        #pragma unroll
        for (int ks = 0; ks < 2; ks++) {
            uint32_t aHi[4][4], aLo[4][4], bHi[4][2], bLo[4][2];
            #pragma unroll
            for (int mf = 0; mf < 4; mf++) {
                uint32_t ao = stg + a_ld + (uint32_t)(mf * 16 * A_STRIDE_B + ks * 32);
                ldsm_x4(aHi[mf], ao + OFF_AHI);
                ldsm_x4(aLo[mf], ao + OFF_ALO);
            }
            #pragma unroll
            for (int nf = 0; nf < 4; nf++) {
                uint32_t bo = stg + b_ld + (uint32_t)(ks * 16 * B_STRIDE_B + nf * 16);
                ldsm_x2t(bHi[nf], bo + OFF_BHI);
                ldsm_x2t(bLo[nf], bo + OFF_BLO);
            }
            #pragma unroll
            for (int mf = 0; mf < 4; mf++)
                #pragma unroll
                for (int nf = 0; nf < 4; nf++) {
                    mma_bf16(acc[mf][nf], aHi[mf], bHi[nf]);
                    mma_bf16(acc[mf][nf], aLo[mf], bHi[nf]);
                    mma_bf16(acc[mf][nf], aHi[mf], bLo[nf]);
                }
        }

        if (c + 1 < NCHUNKS) sts_a(buf ^ 1);
        __syncthreads();
    }

    // ------------------- epilogue ---------------------------------
    float2 bb[4];
    #pragma unroll
    for (int nf = 0; nf < 4; nf++)
        bb[nf] = *reinterpret_cast<const float2*>(bias + n0 + wn * 32 + nf * 8 + li * 2);

    #pragma unroll
    for (int mf = 0; mf < 4; mf++) {
        #pragma unroll
        for (int half = 0; half < 2; half++) {
            int m = m0 + wm * 64 + mf * 16 + gi + half * 8;
            if (m < Mc) {
                int bimg = m / rpi;
                int r    = m % rpi;
                int gh   = ghb + r / nw;
                int gw   = gwb + r % nw;
                size_t obase = ((size_t)(bimg * (GDIM * GDIM) + gh * GDIM + gw)) * DDIM
                             + n0 + wn * 32 + li * 2;
                #pragma unroll
                for (int nf = 0; nf < 4; nf++) {
                    float2 v;
                    v.x = acc[mf][nf][half * 2 + 0] + bb[nf].x;
                    v.y = acc[mf][nf][half * 2 + 1] + bb[nf].y;
                    *reinterpret_cast<float2*>(out + obase + nf * 8) = v;
                }
            }
        }
    }
}

// ---------------------------------------------------------------------------
extern "C" void kernel_launch(void* const* d_in, const int* in_sizes, int n_in,
                              void* d_out, int out_size) {
    const float* images = (const float*)d_in[0];
    const float* W      = (const float*)d_in[1];
    const float* bias   = (const float*)d_in[2];
    float* out          = (float*)d_out;

    cudaFuncSetAttribute(class_gemm_hmma,
                         cudaFuncAttributeMaxDynamicSharedMemorySize, SMEM_TOTAL);

    // 1) per-class bf16-split weights
    build_w_kernel<<<9 * KCLS, 384>>>(W);

    // 2) tensor-core class GEMM: 100 M-tiles x 6 N-tiles
    dim3 grid(100, DDIM / BN);
    class_gemm_hmma<<<grid, 256, SMEM_TOTAL>>>(images, bias, out);
}

// round 4
// speedup vs baseline: 2.5215x; 1.8170x over previous
#include <cuda_runtime.h>
#include <cuda_bf16.h>
#include <cstdint>

// ---------------------------------------------------------------------------
// Problem constants
// ---------------------------------------------------------------------------
#define NIMG   64
#define IMGS   224
#define GDIM   14
#define PSZ    16
#define DDIM   768
#define KCLS   768            // per-class K = 16*16*3
#define ROWEL  (IMGS*3)       // 672 elements per image row
#define IMG_ELEMS (NIMG * IMGS * IMGS * 3)   // 9,633,792

// GEMM tiling
#define BM      128
#define BN      128
#define BK      32
#define NCHUNKS (KCLS / BK)   // 24

// Scratch: split images (2 x 18.4 MB) + split class weights (2 x 10.6 MB)
__device__ __align__(16) __nv_bfloat16 g_img_hi[IMG_ELEMS];
__device__ __align__(16) __nv_bfloat16 g_img_lo[IMG_ELEMS];
__device__ __align__(16) __nv_bfloat16 g_Bhi[9u * KCLS * DDIM];
__device__ __align__(16) __nv_bfloat16 g_Blo[9u * KCLS * DDIM];

// ---------------------------------------------------------------------------
// helpers
// ---------------------------------------------------------------------------
__device__ __forceinline__ uint32_t smem_u32(const void* p) {
    uint32_t a;
    asm("{ .reg .u64 t; cvta.to.shared.u64 t, %1; cvt.u32.u64 %0, t; }"
        : "=r"(a) : "l"(p));
    return a;
}

__device__ __forceinline__ void mma_bf16(float* c, const uint32_t* a, const uint32_t* b) {
    asm volatile(
        "mma.sync.aligned.m16n8k16.row.col.f32.bf16.bf16.f32 "
        "{%0,%1,%2,%3}, {%4,%5,%6,%7}, {%8,%9}, {%0,%1,%2,%3};"
        : "+f"(c[0]), "+f"(c[1]), "+f"(c[2]), "+f"(c[3])
        : "r"(a[0]), "r"(a[1]), "r"(a[2]), "r"(a[3]), "r"(b[0]), "r"(b[1]));
}

__device__ __forceinline__ void ldsm_x4(uint32_t* r, uint32_t addr) {
    asm volatile("ldmatrix.sync.aligned.m8n8.x4.shared.b16 {%0,%1,%2,%3}, [%4];"
                 : "=r"(r[0]), "=r"(r[1]), "=r"(r[2]), "=r"(r[3]) : "r"(addr));
}

__device__ __forceinline__ void ldsm_x2t(uint32_t* r, uint32_t addr) {
    asm volatile("ldmatrix.sync.aligned.m8n8.x2.trans.shared.b16 {%0,%1}, [%2];"
                 : "=r"(r[0]), "=r"(r[1]) : "r"(addr));
}

#define CP_ASYNC16(dst, src) \
    asm volatile("cp.async.cg.shared.global [%0], [%1], 16;" :: "r"(dst), "l"(src))
// predicated: src-size 0 => zero-fill (no gmem read)
#define CP_ASYNC16_P(dst, src, sz) \
    asm volatile("cp.async.cg.shared.global [%0], [%1], 16, %2;" \
                 :: "r"(dst), "l"(src), "r"(sz))
#define CP_COMMIT() asm volatile("cp.async.commit_group;" ::: "memory")
#define CP_WAIT0()  asm volatile("cp.async.wait_group 0;" ::: "memory")

__device__ __forceinline__ void split_pack(float a, float b,
                                           uint32_t& hi, uint32_t& lo) {
    __nv_bfloat16 ha = __float2bfloat16_rn(a);
    __nv_bfloat16 hb = __float2bfloat16_rn(b);
    __nv_bfloat16 la = __float2bfloat16_rn(a - __bfloat162float(ha));
    __nv_bfloat16 lb = __float2bfloat16_rn(b - __bfloat162float(hb));
    hi = ((uint32_t)__bfloat16_as_ushort(hb) << 16) | __bfloat16_as_ushort(ha);
    lo = ((uint32_t)__bfloat16_as_ushort(lb) << 16) | __bfloat16_as_ushort(la);
}

// ---------------------------------------------------------------------------
// Kernel 0: split images into bf16 hi/lo arrays (same HWC indexing).
// ---------------------------------------------------------------------------
__global__ void split_img_kernel(const float* __restrict__ img) {
    int i = blockIdx.x * blockDim.x + threadIdx.x;   // float4 index
    float4 v = reinterpret_cast<const float4*>(img)[i];
    uint32_t h0, l0, h1, l1;
    split_pack(v.x, v.y, h0, l0);
    split_pack(v.z, v.w, h1, l1);
    reinterpret_cast<uint2*>(g_img_hi)[i] = make_uint2(h0, h1);
    reinterpret_cast<uint2*>(g_img_lo)[i] = make_uint2(l0, l1);
}

// ---------------------------------------------------------------------------
// Kernel 1: per-class effective weights, bf16 hi/lo split, layout [cls][k][n].
// ---------------------------------------------------------------------------
__global__ void build_w_kernel(const float* __restrict__ W) {
    int blk  = blockIdx.x;
    int cls  = blk / KCLS;
    int k    = blk % KCLS;
    int clsH = cls / 3, clsW = cls % 3;
    int pp   = k / 3,  cin = k % 3;
    int ph   = pp >> 4, pw = pp & 15;

    int th = (clsH == 0 && ph < 8) ? 0 : (clsH == 2 && ph >= 8) ? 2 : 1;
    int tw = (clsW == 0 && pw < 8) ? 0 : (clsW == 2 && pw >= 8) ? 2 : 1;
    bool i1 = !(th == 2 || tw == 2);
    bool i2 = !(th == 0 || tw == 2);
    bool i3 = !(th == 2 || tw == 0);
    bool i4 = !(th == 0 || tw == 0);

    const float* wb = W + (size_t)(pp * 15 + cin) * DDIM;
    int n = threadIdx.x * 2;

    float s0 = wb[n],     s1 = wb[n + 1];
    if (i1) { s0 += wb[3 * DDIM + n];  s1 += wb[3 * DDIM + n + 1]; }
    if (i2) { s0 += wb[6 * DDIM + n];  s1 += wb[6 * DDIM + n + 1]; }
    if (i3) { s0 += wb[9 * DDIM + n];  s1 += wb[9 * DDIM + n + 1]; }
    if (i4) { s0 += wb[12 * DDIM + n]; s1 += wb[12 * DDIM + n + 1]; }

    uint32_t hi, lo;
    split_pack(s0, s1, hi, lo);
    size_t o = ((size_t)cls * KCLS + k) * DDIM + n;
    *reinterpret_cast<uint32_t*>(&g_Bhi[o]) = hi;
    *reinterpret_cast<uint32_t*>(&g_Blo[o]) = lo;
}

// ---------------------------------------------------------------------------
// Kernel 2: class-partitioned bf16-split HMMA GEMM, all-cp.async pipeline.
// CTA tile 128x128x768, BK=32 double-buffered, 8 warps (2m x 4n).
// ---------------------------------------------------------------------------
#define A_STRIDE_B 80     // bytes per A smem row (32 bf16 + 8 pad)
#define B_STRIDE_B 272    // bytes per B smem row (128 bf16 + 8 pad)
#define OFF_AHI 0
#define OFF_ALO 10240
#define OFF_BHI 20480
#define OFF_BLO 29184
#define STG     37888
#define SMEM_TOTAL (2 * STG)   // 75776

__global__ __launch_bounds__(256, 2)
void class_gemm_hmma(const float* __restrict__ bias,
                     float* __restrict__ out) {
    extern __shared__ __align__(16) char smem[];
    const uint32_t sb = smem_u32(smem);

    const int nhv[3]  = {1, 12, 1};
    const int ghbv[3] = {0, 1, 13};

    // map blockIdx.x -> (class, local m-tile)
    int mtl = blockIdx.x;
    int cls = 8;
    #pragma unroll
    for (int c = 0; c < 9; c++) {
        int tiles_c = (NIMG * nhv[c / 3] * nhv[c % 3] + BM - 1) / BM;
        if (mtl < tiles_c) { cls = c; break; }
        mtl -= tiles_c;
    }
    const int clsH = cls / 3, clsW = cls % 3;
    const int nh = nhv[clsH], nw = nhv[clsW];
    const int ghb = ghbv[clsH], gwb = ghbv[clsW];
    const int rpi = nh * nw;
    const int Mc  = NIMG * rpi;
    const int m0  = mtl * BM;
    const int n0  = blockIdx.y * BN;

    const int t    = threadIdx.x;
    const int wid  = t >> 5, lane = t & 31;
    const int wm   = wid >> 2;
    const int wn   = wid & 3;
    const int gi   = lane >> 2;
    const int li   = lane & 3;
    const int l16  = lane & 15;
    const int lhi  = (lane >> 4) & 1;

    // ---- A cp.async mapping: 2 segments per thread per part ----
    // seg idx = i*256 + t ; row = idx>>2 ; seg = idx&3 (16B = 8 k-elems)
    int arow_[2], aseg_[2];
    uint32_t abase_[2];     // gmem element base for row (hi array)
    uint32_t asz_[2];
    #pragma unroll
    for (int i = 0; i < 2; i++) {
        int idx = i * 256 + t;
        int row = idx >> 2;
        arow_[i] = row;
        aseg_[i] = idx & 3;
        int am = m0 + row;
        bool v = am < Mc;
        int mm = v ? am : 0;
        int bimg = mm / rpi;
        int r    = mm % rpi;
        int gh   = ghb + r / nw;
        int gw   = gwb + r % nw;
        abase_[i] = (uint32_t)((bimg * IMGS + gh * PSZ) * ROWEL + gw * (PSZ * 3));
        asz_[i]   = v ? 16u : 0u;
    }

    const __nv_bfloat16* gBhi = g_Bhi + ((size_t)cls * KCLS) * DDIM + n0;
    const ptrdiff_t bLoOff = g_Blo - g_Bhi;    // constant offset
    const ptrdiff_t iLoOff = g_img_lo - g_img_hi;

    // ldmatrix base offsets
    const uint32_t a_ld = (uint32_t)((wm * 64 + l16) * A_STRIDE_B + lhi * 16);
    const uint32_t b_ld = (uint32_t)(l16 * B_STRIDE_B + wn * 64);

    float acc[4][4][4];
    #pragma unroll
    for (int i = 0; i < 4; i++)
        #pragma unroll
        for (int j = 0; j < 4; j++)
            #pragma unroll
            for (int q = 0; q < 4; q++) acc[i][j][q] = 0.f;

    // ---------------- async tile loader ----------------
    auto issue_loads = [&](int c, int buf) {
        const int kt = c * BK;
        uint32_t dst = sb + buf * STG;
        // A: hi + lo
        #pragma unroll
        for (int i = 0; i < 2; i++) {
            int k   = kt + aseg_[i] * 8;
            int phh = k / 48;
            int rem = k - phh * 48;
            const __nv_bfloat16* src = g_img_hi + abase_[i] + phh * ROWEL + rem;
            uint32_t doff = (uint32_t)(arow_[i] * A_STRIDE_B + aseg_[i] * 16);
            CP_ASYNC16_P(dst + OFF_AHI + doff, src, asz_[i]);
            CP_ASYNC16_P(dst + OFF_ALO + doff, src + iLoOff, asz_[i]);
        }
        // B: hi + lo
        #pragma unroll
        for (int i = 0; i < 2; i++) {
            int idx = i * 256 + t;
            int row = idx >> 4;
            int seg = idx & 15;
            const __nv_bfloat16* src = gBhi + (size_t)(kt + row) * DDIM + seg * 8;
            uint32_t doff = (uint32_t)(row * B_STRIDE_B + seg * 16);
            CP_ASYNC16(dst + OFF_BHI + doff, src);
            CP_ASYNC16(dst + OFF_BLO + doff, src + bLoOff);
        }
        CP_COMMIT();
    };

    // ---------------- pipeline ----------------
    issue_loads(0, 0);

    for (int c = 0; c < NCHUNKS; c++) {
        int buf = c & 1;
        CP_WAIT0();
        __syncthreads();
        if (c + 1 < NCHUNKS) issue_loads(c + 1, buf ^ 1);

        uint32_t stg = sb + buf * STG;
        #pragma unroll
        for (int ks = 0; ks < 2; ks++) {
            uint32_t bHi[4][2], bLo[4][2];
            #pragma unroll
            for (int nf = 0; nf < 4; nf++) {
                uint32_t bo = stg + b_ld + (uint32_t)(ks * 16 * B_STRIDE_B + nf * 16);
                ldsm_x2t(bHi[nf], bo + OFF_BHI);
                ldsm_x2t(bLo[nf], bo + OFF_BLO);
            }
            #pragma unroll
            for (int mf = 0; mf < 4; mf++) {
                uint32_t aHi[4], aLo[4];
                uint32_t ao = stg + a_ld + (uint32_t)(mf * 16 * A_STRIDE_B + ks * 32);
                ldsm_x4(aHi, ao + OFF_AHI);
                ldsm_x4(aLo, ao + OFF_ALO);
                #pragma unroll
                for (int nf = 0; nf < 4; nf++) {
                    mma_bf16(acc[mf][nf], aHi, bHi[nf]);
                    mma_bf16(acc[mf][nf], aLo, bHi[nf]);
                    mma_bf16(acc[mf][nf], aHi, bLo[nf]);
                }
            }
        }
    }

    // ---------------- epilogue ----------------
    float2 bb[4];
    #pragma unroll
    for (int nf = 0; nf < 4; nf++)
        bb[nf] = *reinterpret_cast<const float2*>(bias + n0 + wn * 32 + nf * 8 + li * 2);

    #pragma unroll
    for (int mf = 0; mf < 4; mf++) {
        #pragma unroll
        for (int half = 0; half < 2; half++) {
            int m = m0 + wm * 64 + mf * 16 + gi + half * 8;
            if (m < Mc) {
                int bimg = m / rpi;
                int r    = m % rpi;
                int gh   = ghb + r / nw;
                int gw   = gwb + r % nw;
                size_t obase = ((size_t)(bimg * (GDIM * GDIM) + gh * GDIM + gw)) * DDIM
                             + n0 + wn * 32 + li * 2;
                #pragma unroll
                for (int nf = 0; nf < 4; nf++) {
                    float2 v;
                    v.x = acc[mf][nf][half * 2 + 0] + bb[nf].x;
                    v.y = acc[mf][nf][half * 2 + 1] + bb[nf].y;
                    *reinterpret_cast<float2*>(out + obase + nf * 8) = v;
                }
            }
        }
    }
}

// ---------------------------------------------------------------------------
extern "C" void kernel_launch(void* const* d_in, const int* in_sizes, int n_in,
                              void* d_out, int out_size) {
    const float* images = (const float*)d_in[0];
    const float* W      = (const float*)d_in[1];
    const float* bias   = (const float*)d_in[2];
    float* out          = (float*)d_out;

    cudaFuncSetAttribute(class_gemm_hmma,
                         cudaFuncAttributeMaxDynamicSharedMemorySize, SMEM_TOTAL);

    split_img_kernel<<<IMG_ELEMS / 4 / 256, 256>>>(images);
    build_w_kernel<<<9 * KCLS, 384>>>(W);

    dim3 grid(100, DDIM / BN);
    class_gemm_hmma<<<grid, 256, SMEM_TOTAL>>>(bias, out);
}